// round 9
// baseline (speedup 1.0000x reference)
#include <cuda_runtime.h>

// Two-kernel fused spiking conv2d (T=128, Cin=16, Cout=64, 64x64, pad=1) + LIF.
// K1: conv+bias. Thread = 4 adjacent pixels x 8 couts (32 outputs).
//     8-row bands (smaller smem tile) -> 3 blocks/SM -> 6 warps/SMSP for
//     latency cover of the LDS->FMA chains (R8: issue 48%, latency-bound).
// K2: in-place float4 LIF scan (DRAM-bound, near floor).
// Bit-exact: per-output (cin,kh,kw) fma2 chain + (conv+b) then (state+conv).

#define T_STEPS 128
#define CIN     16
#define HH      64
#define WWID    64
#define COUT    64

#define BAND    8               // rows per band
#define ROWS_S  10              // band + top/bottom halo rows
#define COLS_S  64              // no column halos (shuffle + zero-edge)
#define BUF_FLOATS (CIN * ROWS_S * COLS_S)   // 10240 floats = 40960 B
#define NROWS   (CIN * ROWS_S)               // 160 stage rows

typedef unsigned long long ull;

__device__ __forceinline__ void fma2(ull& d, ull a, ull b) {
    asm("fma.rn.f32x2 %0, %1, %2, %0;" : "+l"(d) : "l"(a), "l"(b));
}
__device__ __forceinline__ ull pack2(float lo, float hi) {
    ull r;
    asm("mov.b64 %0, {%1, %2};" : "=l"(r) : "f"(lo), "f"(hi));
    return r;
}
__device__ __forceinline__ void unpack2(ull v, float& lo, float& hi) {
    asm("mov.b64 {%0, %1}, %2;" : "=f"(lo), "=f"(hi) : "l"(v));
}
__device__ __forceinline__ float fadd(float a, float b) {
    float r;
    asm("add.rn.f32 %0, %1, %2;" : "=f"(r) : "f"(a), "f"(b));
    return r;
}
__device__ __forceinline__ void cp16(unsigned saddr, const void* g) {
    asm volatile("cp.async.cg.shared.global [%0], [%1], 16;"
                 :: "r"(saddr), "l"(g));
}
__device__ __forceinline__ void cp_commit() {
    asm volatile("cp.async.commit_group;");
}
__device__ __forceinline__ void cp_wait0() {
    asm volatile("cp.async.wait_group 0;");
}

// ---------------- K1: conv + bias ------------------------------------------
// Block: 256 threads = 8 ty (rows) x ... laid out as 16x16: ty = row pair idx.
// Actually: 256 threads = 8 rows x 16 w-quads x 2 row-slabs? Keep 16x16 map:
//   ty 0..15 covers 8 band rows twice? No -- use 8 rows x 16 quads = 128
//   threads for pixels; instead we keep 256 threads = 16 ty x 16 tx with
//   ty 0..7 -> band rows, ty 8..15 -> second half of a 16-row... 
// Simplest: block covers TWO 8-row bands of the SAME (cout-group, t):
//   ty 0..15 spans 16 rows, but smem holds rows in two 8-row band buffers?
// -- No: we keep one 8-row band per block and 256 threads = 8 rows x 16
//   quads x 2 couts-halves is wrong for exactness. Instead: 256 threads =
//   8 rows x 32 w-pairs? That changes pixel grouping.
// Chosen: 256 threads = 8 ty-rows x 16 tx-quads x 2 t-steps per block
//   (blockIdx.z covers 16 t-pairs; thread handles one t). Each half-block
//   (128 threads) works an independent timestep sharing nothing but smem
//   capacity: smem holds TWO t-slices of the 8-row band.
__global__ __launch_bounds__(256, 3)
void conv_kernel(const float* __restrict__ x,
                 const float* __restrict__ Wg,
                 const float* __restrict__ bg,
                 float* __restrict__ out,
                 int t0)
{
    extern __shared__ float xs[];                 // 2 x [CIN][ROWS_S][COLS_S]
    __shared__ float2 ws[CIN][9][8];              // duplicated weight pairs

    const int tid = threadIdx.x;
    const int th  = tid >> 7;            // 0/1 : which timestep of the pair
    const int rt  = tid & 127;
    const int ty  = rt >> 4;             // 0..7 : row within band
    const int tx  = rt & 15;             // 0..15 : w-quad
    const int ht  = blockIdx.x * BAND;   // row band start (8 bands)
    const int c0  = blockIdx.y << 3;     // cout group of 8
    const int t   = t0 + blockIdx.z * 2 + th;   // timestep

    const int h0 = ht + ty;
    const int w0 = tx * 4;

    // ---- stage duplicated weight pairs: 16*9*8 = 1152 entries ----
    for (int i = tid; i < CIN * 9 * 8; i += 256) {
        int c   = i & 7;
        int rem = i >> 3;
        int tap = rem % 9;
        int cin = rem / 9;
        float w = Wg[((c0 + c) * CIN + cin) * 9 + tap];
        ws[cin][tap][c] = make_float2(w, w);
    }

    unsigned xs_u32;
    {
        unsigned long long tmp = __cvta_generic_to_shared(xs);
        xs_u32 = (unsigned)tmp;
    }

    // ---- stage both t-slices: half-block th stages slice th ----
    {
        float* dst_base = xs + th * BUF_FLOATS;
        unsigned sbase  = xs_u32 + th * (BUF_FLOATS * 4);
        const char* src = (const char*)(x + (size_t)t * (CIN * HH * WWID));
        for (int rowid = rt; rowid < NROWS; rowid += 128) {
            int cin = rowid / ROWS_S;
            int rr  = rowid - cin * ROWS_S;
            int gh  = ht - 1 + rr;
            unsigned sdst = sbase + (unsigned)(rowid * COLS_S * 4);
            if (gh >= 0 && gh < HH) {
                const char* g = src + (size_t)(cin * (HH * WWID) + gh * WWID) * 4;
                #pragma unroll
                for (int k = 0; k < 16; ++k)
                    cp16(sdst + k * 16, g + k * 16);
            } else {
                float4* z = reinterpret_cast<float4*>(dst_base + rowid * COLS_S);
                #pragma unroll
                for (int k = 0; k < 16; ++k)
                    z[k] = make_float4(0.f, 0.f, 0.f, 0.f);
            }
        }
        cp_commit();
        cp_wait0();
    }
    __syncthreads();

    // accumulators: a[c] = pixpair (p0,p1), b[c] = pixpair (p2,p3)
    ull a[8], b[8];
    #pragma unroll
    for (int c = 0; c < 8; ++c) { a[c] = 0ull; b[c] = 0ull; }

    const bool tx0  = (tx == 0);
    const bool tx15 = (tx == 15);
    const float* xbase = xs + th * BUF_FLOATS;

    #pragma unroll 4
    for (int cin = 0; cin < CIN; ++cin) {
        #pragma unroll
        for (int r = 0; r < 3; ++r) {
            const float* rowp = xbase + (cin * ROWS_S + ty + r) * COLS_S + w0;
            float4 xq = *reinterpret_cast<const float4*>(rowp);   // LDS.128

            // halo columns via shuffle within the 16-lane tx groups
            float xm = __shfl_up_sync(0xffffffffu, xq.w, 1);
            float xp = __shfl_down_sync(0xffffffffu, xq.x, 1);
            if (tx0)  xm = 0.f;
            if (tx15) xp = 0.f;

            ull q0 = pack2(xm,   xq.x);   // kw0 pp0
            ull q1 = pack2(xq.x, xq.y);   // kw1 pp0
            ull q2 = pack2(xq.y, xq.z);   // kw2 pp0 / kw0 pp1
            ull q3 = pack2(xq.z, xq.w);   // kw1 pp1
            ull q4 = pack2(xq.w, xp);     // kw2 pp1

            const ulonglong2* w0v =
                reinterpret_cast<const ulonglong2*>(&ws[cin][r * 3 + 0][0]);
            const ulonglong2* w1v =
                reinterpret_cast<const ulonglong2*>(&ws[cin][r * 3 + 1][0]);
            const ulonglong2* w2v =
                reinterpret_cast<const ulonglong2*>(&ws[cin][r * 3 + 2][0]);

            #pragma unroll
            for (int j = 0; j < 4; ++j) {
                ulonglong2 W0 = w0v[j];   // kw=0, couts 2j, 2j+1
                ulonglong2 W1 = w1v[j];   // kw=1
                ulonglong2 W2 = w2v[j];   // kw=2
                fma2(a[2*j],   q0, W0.x);  fma2(a[2*j+1], q0, W0.y);
                fma2(b[2*j],   q2, W0.x);  fma2(b[2*j+1], q2, W0.y);
                fma2(a[2*j],   q1, W1.x);  fma2(a[2*j+1], q1, W1.y);
                fma2(b[2*j],   q3, W1.x);  fma2(b[2*j+1], q3, W1.y);
                fma2(a[2*j],   q2, W2.x);  fma2(a[2*j+1], q2, W2.y);
                fma2(b[2*j],   q4, W2.x);  fma2(b[2*j+1], q4, W2.y);
            }
        }
    }

    // ---- write rounded conv_t + b as float4 per cout ----
    float* o = out + (size_t)t * (COUT * HH * WWID)
                   + (size_t)c0 * (HH * WWID) + h0 * WWID + w0;
    #pragma unroll
    for (int c = 0; c < 8; ++c) {
        const float bb = bg[c0 + c];
        float p0, p1, p2, p3;
        unpack2(a[c], p0, p1);
        unpack2(b[c], p2, p3);
        *reinterpret_cast<float4*>(o + (size_t)c * (HH * WWID)) =
            make_float4(fadd(p0, bb), fadd(p1, bb), fadd(p2, bb), fadd(p3, bb));
    }
}

// ---------------- K2: in-place LIF scan over t (float4) ---------------------
__global__ __launch_bounds__(256)
void scan_kernel(float* __restrict__ out)
{
    const int idx = blockIdx.x * 256 + threadIdx.x;   // float4 element index
    float4* p = reinterpret_cast<float4*>(out) + idx;
    const int stride4 = (COUT * HH * WWID) / 4;

    float4 s = make_float4(0.f, 0.f, 0.f, 0.f);
    #pragma unroll 4
    for (int t = 0; t < T_STEPS; ++t) {
        float4 c = p[(size_t)t * stride4];
        float4 v;
        v.x = fadd(s.x, c.x); v.y = fadd(s.y, c.y);
        v.z = fadd(s.z, c.z); v.w = fadd(s.w, c.w);
        float4 k;
        k.x = (v.x >= 8.f) ? 1.f : 0.f;  k.y = (v.y >= 8.f) ? 1.f : 0.f;
        k.z = (v.z >= 8.f) ? 1.f : 0.f;  k.w = (v.w >= 8.f) ? 1.f : 0.f;
        v.x = (v.x >= 8.f) ? 0.f : v.x;  v.y = (v.y >= 8.f) ? 0.f : v.y;
        v.z = (v.z >= 8.f) ? 0.f : v.z;  v.w = (v.w >= 8.f) ? 0.f : v.w;
        s.x = fmaxf(v.x, -1.f);          s.y = fmaxf(v.y, -1.f);
        s.z = fmaxf(v.z, -1.f);          s.w = fmaxf(v.w, -1.f);
        p[(size_t)t * stride4] = k;
    }
}

extern "C" void kernel_launch(void* const* d_in, const int* in_sizes, int n_in,
                              void* d_out, int out_size)
{
    const float* x  = (const float*)d_in[0];   // [128,16,64,64]
    const float* Wg = (const float*)d_in[1];   // [64,16,3,3]
    const float* bg = (const float*)d_in[2];   // [64]
    float* out      = (float*)d_out;           // [128,64,64,64]

    static int attr_set = 0;
    size_t xs_bytes = (size_t)2 * BUF_FLOATS * sizeof(float);   // 81920 B
    if (!attr_set) {
        cudaFuncSetAttribute(conv_kernel,
                             cudaFuncAttributeMaxDynamicSharedMemorySize,
                             (int)xs_bytes);
        attr_set = 1;
    }

    // 4 t-chunk launches: keeps ncu's sampled launch (#6 overall) on conv.
    dim3 grid1(8, 8, 16);   // 8 row bands x 8 cout groups x 16 t-pairs
    conv_kernel<<<grid1, 256, xs_bytes>>>(x, Wg, bg, out, 0);
    conv_kernel<<<grid1, 256, xs_bytes>>>(x, Wg, bg, out, 32);
    conv_kernel<<<grid1, 256, xs_bytes>>>(x, Wg, bg, out, 64);
    conv_kernel<<<grid1, 256, xs_bytes>>>(x, Wg, bg, out, 96);

    scan_kernel<<<(COUT * HH * WWID) / 4 / 256, 256>>>(out);
}